// round 6
// baseline (speedup 1.0000x reference)
#include <cuda_runtime.h>

// MI loss over two 2^25 fp32 arrays — SINGLE fused kernel.
// joint_hist == hist_x + hist_y -> only two 30-bin histograms needed.
// Hot loop: per-lane-private smem histograms (bank==lane, conflict-free,
// no atomics), 7 blocks/SM, 2 float4 loads in flight per thread.
// Flush: 60 global atomicAdds per block (spread addresses -> ~free).
// Last block (ticket protocol) runs the lane-parallel fp64 epilogue and
// resets global state so every graph replay sees identical conditions.

#define BINS 30
#define NBIN_PAD 32          // 30 bins + trash slot 30 (never flushed)
#define THREADS 256
#define WARPS (THREADS / 32)
#define BPA 518              // blocks per array: 2*518 = 1036 = 7 per SM
#define NBLOCKS (2 * BPA)

__device__ unsigned int g_hist[2 * NBIN_PAD];  // zero-init BSS; reset each run
__device__ unsigned int g_done;                // ticket counter; reset each run

__global__ void __launch_bounds__(THREADS, 7) mi_fused_kernel(
    const float* __restrict__ x, const float* __restrict__ y,
    int nx, int ny, float* __restrict__ out)
{
    // 8 warps * 32 slots * 32 lanes * 4B = 32 KB
    __shared__ unsigned int sh[WARPS * NBIN_PAD * 32];
    __shared__ int s_last;

    for (int i = threadIdx.x; i < WARPS * NBIN_PAD * 32; i += THREADS) sh[i] = 0u;
    __syncthreads();

    const int which = (blockIdx.x >= BPA) ? 1 : 0;
    const float* __restrict__ src = which ? y : x;
    const int n = which ? ny : nx;
    const int bid = which ? ((int)blockIdx.x - BPA) : (int)blockIdx.x;

    const int warp = threadIdx.x >> 5;
    const int lane = threadIdx.x & 31;
    // lane-private column: addr = warp*4096B + slot*128B + lane*4B
    // bank(addr) == lane for every slot -> conflict-free RMW.
    unsigned int* __restrict__ h = sh + warp * (NBIN_PAD * 32) + lane;

    const float4* __restrict__ v4 = (const float4*)src;
    const int n4 = n >> 2;
    const int stride = BPA * THREADS;

    // R3-exact binning (rel_err 7.28e-7): t = fma(v,3.75,15);
    // b = min(floor(t), 29); out-of-range -> trash slot 30.
#define PROC(val) {                                          \
        float t = fmaf((val), 3.75f, 15.0f);                 \
        int b = __float2int_rd(t);                           \
        b = min(b, 29);                                      \
        bool ok = (t >= 0.0f) && (t <= 30.0f);               \
        if (!ok) b = 30;                                     \
        h[b << 5] += 1u; }

    // Two independent float4 loads per iteration -> 2 cache lines in
    // flight per thread before the smem RMW chain starts.
    int i = bid * THREADS + threadIdx.x;
    for (; i + stride < n4; i += 2 * stride) {
        float4 a = v4[i];
        float4 b4 = v4[i + stride];
        PROC(a.x)  PROC(a.y)  PROC(a.z)  PROC(a.w)
        PROC(b4.x) PROC(b4.y) PROC(b4.z) PROC(b4.w)
    }
    if (i < n4) {
        float4 a = v4[i];
        PROC(a.x)  PROC(a.y)  PROC(a.z)  PROC(a.w)
    }

    // scalar tail (empty when n % 4 == 0)
    if (bid == 0) {
        for (int j = (n4 << 2) + threadIdx.x; j < n; j += THREADS) {
            float val = src[j];
            PROC(val)
        }
    }
#undef PROC

    __syncthreads();

    // Reduce 30 bins x 32 lanes over 8 warp-copies -> 60 spread global
    // atomics per block (REDG-cheap).
    for (int p = threadIdx.x; p < BINS * 32; p += THREADS) {
        int b = p >> 5;
        int l = p & 31;
        unsigned int s = 0;
        #pragma unroll
        for (int w = 0; w < WARPS; w++)
            s += sh[w * (NBIN_PAD * 32) + (b << 5) + l];
        #pragma unroll
        for (int off = 16; off; off >>= 1)
            s += __shfl_xor_sync(0xffffffffu, s, off);
        if (l == 0 && s)
            atomicAdd(&g_hist[which * NBIN_PAD + b], s);
    }

    // Ticket: last block to finish runs the epilogue.
    if (threadIdx.x == 0) {
        __threadfence();
        unsigned int t = atomicAdd(&g_done, 1u);
        s_last = (t == NBLOCKS - 1);
    }
    __syncthreads();
    if (!s_last) return;

    if (warp == 0) {
        __threadfence();   // order our reads after everyone's atomics
        bool live = (lane < BINS);
        // atomicAdd(ptr,0): L2-coherent read of the final totals.
        double hx = live ? (double)atomicAdd(&g_hist[lane], 0u) : 0.0;
        double hy = live ? (double)atomicAdd(&g_hist[NBIN_PAD + lane], 0u) : 0.0;

        double Sx = hx, Sy = hy;
        #pragma unroll
        for (int off = 16; off; off >>= 1) {
            Sx += __shfl_xor_sync(0xffffffffu, Sx, off);
            Sy += __shfl_xor_sync(0xffffffffu, Sy, off);
        }
        double Sj = Sx + Sy;

        double term = 0.0, lx = 0.0;
        if (live) {
            double jp = (hx + hy) / Sj;
            double py = hy / Sy;
            double px = hx / Sx;
            term = jp * (log(jp) - log(py));
            lx = log(px);
        }
        #pragma unroll
        for (int off = 16; off; off >>= 1) {
            term += __shfl_xor_sync(0xffffffffu, term, off);
            lx   += __shfl_xor_sync(0xffffffffu, lx, off);
        }
        if (lane == 0) {
            double mi = (double)BINS * term - lx;
            out[0] = (float)(-mi);
            g_done = 0;                     // reset for next graph replay
        }
        // reset histogram for next graph replay (lanes cover all 64 slots)
        g_hist[lane] = 0u;
        g_hist[NBIN_PAD + lane] = 0u;
    }
}

extern "C" void kernel_launch(void* const* d_in, const int* in_sizes, int n_in,
                              void* d_out, int out_size) {
    const float* x = (const float*)d_in[0];
    const float* y = (const float*)d_in[1];
    int nx = in_sizes[0];
    int ny = in_sizes[1];

    mi_fused_kernel<<<NBLOCKS, THREADS>>>(x, y, nx, ny, (float*)d_out);
}

// round 7
// speedup vs baseline: 1.0500x; 1.0500x over previous
#include <cuda_runtime.h>

// MI loss over two 2^25 fp32 arrays — single fused kernel.
// joint_hist == hist_x + hist_y -> only two 30-bin histograms needed.
// Hot loop: 4 independent float4 loads batched into registers (MLP=4,
// hides 577cyc DRAM latency), then per-lane-private smem histogram RMW
// (bank==lane, conflict-free, no atomics).
// Flush: 60 spread global atomicAdds per block (~free).
// Last block (ticket) runs the lane-parallel fp64 epilogue and resets
// global state so every graph replay sees identical conditions.

#define BINS 30
#define NBIN_PAD 32          // 30 bins + trash slot 30 (never flushed)
#define THREADS 256
#define WARPS (THREADS / 32)
#define BPA 518              // blocks per array; 2*518 = 1036 blocks
#define NBLOCKS (2 * BPA)
#define MLP 4                // independent float4 loads in flight per thread

__device__ unsigned int g_hist[2 * NBIN_PAD];  // zero-init BSS; reset each run
__device__ unsigned int g_done;                // ticket counter; reset each run

__global__ void __launch_bounds__(THREADS) mi_fused_kernel(
    const float* __restrict__ x, const float* __restrict__ y,
    int nx, int ny, float* __restrict__ out)
{
    // 8 warps * 32 slots * 32 lanes * 4B = 32 KB
    __shared__ unsigned int sh[WARPS * NBIN_PAD * 32];
    __shared__ int s_last;

    for (int i = threadIdx.x; i < WARPS * NBIN_PAD * 32; i += THREADS) sh[i] = 0u;
    __syncthreads();

    const int which = (blockIdx.x >= BPA) ? 1 : 0;
    const float* __restrict__ src = which ? y : x;
    const int n = which ? ny : nx;
    const int bid = which ? ((int)blockIdx.x - BPA) : (int)blockIdx.x;

    const int warp = threadIdx.x >> 5;
    const int lane = threadIdx.x & 31;
    // lane-private column: addr = warp*4096B + slot*128B + lane*4B
    // bank(addr) == lane for every slot -> conflict-free RMW.
    unsigned int* __restrict__ h = sh + warp * (NBIN_PAD * 32) + lane;

    const float4* __restrict__ v4 = (const float4*)src;
    const int n4 = n >> 2;
    const int stride = BPA * THREADS;

    // R3-exact binning (rel_err 7.28e-7): t = fma(v,3.75,15);
    // b = min(floor(t), 29); out-of-range -> trash slot 30.
#define PROC(val) {                                          \
        float t = fmaf((val), 3.75f, 15.0f);                 \
        int b = __float2int_rd(t);                           \
        b = min(b, 29);                                      \
        bool ok = (t >= 0.0f) && (t <= 30.0f);               \
        if (!ok) b = 30;                                     \
        h[b << 5] += 1u; }

    // Main loop: MLP independent loads issued back-to-back, THEN the smem
    // RMW chains. Keeps 16 sectors in flight per thread.
    int i = bid * THREADS + threadIdx.x;
    for (; i + (MLP - 1) * stride < n4; i += MLP * stride) {
        float4 v[MLP];
        #pragma unroll
        for (int u = 0; u < MLP; u++) v[u] = v4[i + u * stride];
        #pragma unroll
        for (int u = 0; u < MLP; u++) {
            PROC(v[u].x) PROC(v[u].y) PROC(v[u].z) PROC(v[u].w)
        }
    }
    // remainder float4s (up to MLP-1 per thread)
    for (; i < n4; i += stride) {
        float4 v = v4[i];
        PROC(v.x) PROC(v.y) PROC(v.z) PROC(v.w)
    }
    // scalar tail (empty when n % 4 == 0)
    if (bid == 0) {
        for (int j = (n4 << 2) + threadIdx.x; j < n; j += THREADS) {
            float val = src[j];
            PROC(val)
        }
    }
#undef PROC

    __syncthreads();

    // Reduce 30 bins x 32 lanes over 8 warp-copies -> 60 spread global
    // atomics per block.
    for (int p = threadIdx.x; p < BINS * 32; p += THREADS) {
        int b = p >> 5;
        int l = p & 31;
        unsigned int s = 0;
        #pragma unroll
        for (int w = 0; w < WARPS; w++)
            s += sh[w * (NBIN_PAD * 32) + (b << 5) + l];
        #pragma unroll
        for (int off = 16; off; off >>= 1)
            s += __shfl_xor_sync(0xffffffffu, s, off);
        if (l == 0 && s)
            atomicAdd(&g_hist[which * NBIN_PAD + b], s);
    }

    // Ticket: last block to finish runs the epilogue.
    if (threadIdx.x == 0) {
        __threadfence();
        unsigned int t = atomicAdd(&g_done, 1u);
        s_last = (t == NBLOCKS - 1);
    }
    __syncthreads();
    if (!s_last) return;

    if (warp == 0) {
        __threadfence();   // order our reads after everyone's atomics
        bool live = (lane < BINS);
        // atomicAdd(ptr,0): L2-coherent read of final totals.
        double hx = live ? (double)atomicAdd(&g_hist[lane], 0u) : 0.0;
        double hy = live ? (double)atomicAdd(&g_hist[NBIN_PAD + lane], 0u) : 0.0;

        double Sx = hx, Sy = hy;
        #pragma unroll
        for (int off = 16; off; off >>= 1) {
            Sx += __shfl_xor_sync(0xffffffffu, Sx, off);
            Sy += __shfl_xor_sync(0xffffffffu, Sy, off);
        }
        double Sj = Sx + Sy;

        double term = 0.0, lx = 0.0;
        if (live) {
            double jp = (hx + hy) / Sj;
            double py = hy / Sy;
            double px = hx / Sx;
            term = jp * (log(jp) - log(py));
            lx = log(px);
        }
        #pragma unroll
        for (int off = 16; off; off >>= 1) {
            term += __shfl_xor_sync(0xffffffffu, term, off);
            lx   += __shfl_xor_sync(0xffffffffu, lx, off);
        }
        if (lane == 0) {
            double mi = (double)BINS * term - lx;
            out[0] = (float)(-mi);
            g_done = 0;                     // reset for next graph replay
        }
        // reset histogram for next graph replay
        g_hist[lane] = 0u;
        g_hist[NBIN_PAD + lane] = 0u;
    }
}

extern "C" void kernel_launch(void* const* d_in, const int* in_sizes, int n_in,
                              void* d_out, int out_size) {
    const float* x = (const float*)d_in[0];
    const float* y = (const float*)d_in[1];
    int nx = in_sizes[0];
    int ny = in_sizes[1];

    mi_fused_kernel<<<NBLOCKS, THREADS>>>(x, y, nx, ny, (float*)d_out);
}

// round 8
// speedup vs baseline: 1.0989x; 1.0466x over previous
#include <cuda_runtime.h>

// MI loss over two 2^25 fp32 arrays — single fused kernel.
// joint_hist == hist_x + hist_y -> only two 30-bin histograms needed.
// Hot loop: R5's exact shape (plain grid-stride, unroll 8, launch_bounds
// (256,7)) — ptxas software-pipelines 8 load+RMW chains; measured fastest.
// Per-lane-private smem histogram (bank==lane, conflict-free, no atomics).
// Flush: 60 spread global atomicAdds per block (~free).
// Last block (ticket) runs the lane-parallel fp64 epilogue and resets
// global state so every graph replay sees identical conditions.

#define BINS 30
#define NBIN_PAD 32          // 30 bins + trash slot 30 (never flushed)
#define THREADS 256
#define WARPS (THREADS / 32)
#define BPA 518              // blocks per array; 2*518 = 1036 = 7 per SM
#define NBLOCKS (2 * BPA)

__device__ unsigned int g_hist[2 * NBIN_PAD];  // zero-init BSS; reset each run
__device__ unsigned int g_done;                // ticket counter; reset each run

__global__ void __launch_bounds__(THREADS, 7) mi_fused_kernel(
    const float* __restrict__ x, const float* __restrict__ y,
    int nx, int ny, float* __restrict__ out)
{
    // 8 warps * 32 slots * 32 lanes * 4B = 32 KB
    __shared__ unsigned int sh[WARPS * NBIN_PAD * 32];
    __shared__ int s_last;

    for (int i = threadIdx.x; i < WARPS * NBIN_PAD * 32; i += THREADS) sh[i] = 0u;
    __syncthreads();

    const int which = (blockIdx.x >= BPA) ? 1 : 0;
    const float* __restrict__ src = which ? y : x;
    const int n = which ? ny : nx;
    const int bid = which ? ((int)blockIdx.x - BPA) : (int)blockIdx.x;

    const int warp = threadIdx.x >> 5;
    const int lane = threadIdx.x & 31;
    // lane-private column: addr = warp*4096B + slot*128B + lane*4B
    // bank(addr) == lane for every slot -> conflict-free RMW.
    unsigned int* __restrict__ h = sh + warp * (NBIN_PAD * 32) + lane;

    const float4* __restrict__ v4 = (const float4*)src;
    const int n4 = n >> 2;
    const int stride = BPA * THREADS;

    // R3-exact binning (rel_err 7.28e-7): t = fma(v,3.75,15);
    // b = min(floor(t), 29); out-of-range -> trash slot 30.
#define PROC(val) {                                          \
        float t = fmaf((val), 3.75f, 15.0f);                 \
        int b = __float2int_rd(t);                           \
        b = min(b, 29);                                      \
        bool ok = (t >= 0.0f) && (t <= 30.0f);               \
        if (!ok) b = 30;                                     \
        h[b << 5] += 1u; }

    // R5's measured-fastest loop shape: let ptxas pipeline it.
    #pragma unroll 8
    for (int i = bid * THREADS + threadIdx.x; i < n4; i += stride) {
        float4 v = v4[i];
        PROC(v.x) PROC(v.y) PROC(v.z) PROC(v.w)
    }

    // scalar tail (empty when n % 4 == 0)
    if (bid == 0) {
        for (int j = (n4 << 2) + threadIdx.x; j < n; j += THREADS) {
            float val = src[j];
            PROC(val)
        }
    }
#undef PROC

    __syncthreads();

    // Reduce 30 bins x 32 lanes over 8 warp-copies -> 60 spread global
    // atomics per block.
    for (int p = threadIdx.x; p < BINS * 32; p += THREADS) {
        int b = p >> 5;
        int l = p & 31;
        unsigned int s = 0;
        #pragma unroll
        for (int w = 0; w < WARPS; w++)
            s += sh[w * (NBIN_PAD * 32) + (b << 5) + l];
        #pragma unroll
        for (int off = 16; off; off >>= 1)
            s += __shfl_xor_sync(0xffffffffu, s, off);
        if (l == 0 && s)
            atomicAdd(&g_hist[which * NBIN_PAD + b], s);
    }

    // Ticket: last block to finish runs the epilogue.
    if (threadIdx.x == 0) {
        __threadfence();
        unsigned int t = atomicAdd(&g_done, 1u);
        s_last = (t == NBLOCKS - 1);
    }
    __syncthreads();
    if (!s_last) return;

    if (warp == 0) {
        __threadfence();   // order our reads after everyone's atomics
        bool live = (lane < BINS);
        // atomicAdd(ptr,0): L2-coherent read of final totals.
        double hx = live ? (double)atomicAdd(&g_hist[lane], 0u) : 0.0;
        double hy = live ? (double)atomicAdd(&g_hist[NBIN_PAD + lane], 0u) : 0.0;

        double Sx = hx, Sy = hy;
        #pragma unroll
        for (int off = 16; off; off >>= 1) {
            Sx += __shfl_xor_sync(0xffffffffu, Sx, off);
            Sy += __shfl_xor_sync(0xffffffffu, Sy, off);
        }
        double Sj = Sx + Sy;

        double term = 0.0, lx = 0.0;
        if (live) {
            double jp = (hx + hy) / Sj;
            double py = hy / Sy;
            double px = hx / Sx;
            term = jp * (log(jp) - log(py));
            lx = log(px);
        }
        #pragma unroll
        for (int off = 16; off; off >>= 1) {
            term += __shfl_xor_sync(0xffffffffu, term, off);
            lx   += __shfl_xor_sync(0xffffffffu, lx, off);
        }
        if (lane == 0) {
            double mi = (double)BINS * term - lx;
            out[0] = (float)(-mi);
            g_done = 0;                     // reset for next graph replay
        }
        // reset histogram for next graph replay
        g_hist[lane] = 0u;
        g_hist[NBIN_PAD + lane] = 0u;
    }
}

extern "C" void kernel_launch(void* const* d_in, const int* in_sizes, int n_in,
                              void* d_out, int out_size) {
    const float* x = (const float*)d_in[0];
    const float* y = (const float*)d_in[1];
    int nx = in_sizes[0];
    int ny = in_sizes[1];

    mi_fused_kernel<<<NBLOCKS, THREADS>>>(x, y, nx, ny, (float*)d_out);
}